// round 9
// baseline (speedup 1.0000x reference)
#include <cuda_runtime.h>

#define HH 128
#define WW 128
#define NIMG 2
#define NC 21
#define PL (HH * WW)
#define NBLK (4 * HH * NIMG)   // 1024 blocks: (xquarter, y, n)

// exp(x) = exp2(x * log2 e); we need exp(-0.5 v) = exp2(v * -0.72134752)
#define NEG_HALF_LOG2E (-0.72134752f)

__device__ double   g_accs[32];   // spread accumulators (zero-init; self-reset)
__device__ unsigned g_cnt;

typedef unsigned long long u64;

// ---- packed f32x2 helpers (FFMA2 path; ptxas never emits these from C++) ----
__device__ __forceinline__ u64 pk(float lo, float hi) {
    u64 r;
    asm("mov.b64 %0, {%1, %2};" : "=l"(r) : "f"(lo), "f"(hi));
    return r;
}
__device__ __forceinline__ void fma2(u64& d, u64 a, u64 b) {
    asm("fma.rn.f32x2 %0, %1, %2, %0;" : "+l"(d) : "l"(a), "l"(b));
}
__device__ __forceinline__ float2 unpk(u64 v) {
    float lo, hi;
    asm("mov.b64 {%0, %1}, %2;" : "=f"(lo), "=f"(hi) : "l"(v));
    return make_float2(lo, hi);
}

// exp(-k^2/72) for k = 0..5 (compile-time folded)
__device__ __forceinline__ constexpr float exy_tab(int k) {
    constexpr float E[6] = {1.0f, 0.98620712f, 0.94595947f,
                            0.88249690f, 0.80073740f, 0.70664828f};
    return E[k];
}

// ---------------------------------------------------------------------------
// Phase-2 worker: warp-group G handles slots with slot%4 == G.
// (r, dx, slot, exy) compile-time. Non-forward slots written 0.
// ---------------------------------------------------------------------------
template <int G>
__device__ __forceinline__ float phase2_slots(const float (*pool)[3][48],
                                              float (*K2s)[32],
                                              int px, int x, int y) {
    const int c0 = px + 8;
    const float r0 = pool[0][0][c0];
    const float g0 = pool[0][1][c0];
    const float b0 = pool[0][2][c0];
    float t1 = 0.0f;
#pragma unroll
    for (int r = 0; r <= 5; r++) {
#pragma unroll
        for (int dxi = 0; dxi < 11; dxi++) {
            const int slot = r * 11 + dxi;
            if ((slot & 3) == G) {
                const int dx = dxi - 5;
                const bool fwd = (r > 0) || (dx > 0);
                float k2 = 0.0f;
                if (fwd && (y + r < HH) && ((unsigned)(x + dx) < (unsigned)WW)) {
                    const float exy = exy_tab(r) * exy_tab(dx < 0 ? -dx : dx);
                    const int ci = c0 + dx;
                    float dr = pool[r][0][ci] - r0;
                    float dg = pool[r][1][ci] - g0;
                    float db = pool[r][2][ci] - b0;
                    float q  = fmaf(dr, dr, fmaf(dg, dg, db * db));
                    float e  = exp2f(q * NEG_HALF_LOG2E);
                    k2 = fmaf(1.8f * exy, e, 0.2f * exy);
                }
                t1 += k2;
                K2s[slot][px] = k2;
            }
        }
    }
    return t1;
}

// ---------------------------------------------------------------------------
// ONE fused kernel. Block = quarter-row (32 px), 128 threads, 8 blocks/SM
// -> 1184 CTA capacity >= 1024 grid: SINGLE WAVE, occ ceiling 50%.
// Phase 3 packed f32x2; k2 pairs loaded straight from smem as u64 (no packs).
// ---------------------------------------------------------------------------
__global__ void __launch_bounds__(128, 8) crf_fused(const float* __restrict__ Y,
                                                    const float* __restrict__ rgb,
                                                    float* __restrict__ out) {
    const int xq = blockIdx.x;           // 0..3
    const int y  = blockIdx.y;           // 0..127
    const int n  = blockIdx.z;           // 0..1
    const int x0base = xq * 32;
    const int tid = threadIdx.x;

    __shared__ float pool[6][3][48];     // pooled rgb, cols x0base-8 .. x0base+39
    __shared__ float K2s[66][32];        // slot = r*11 + (dx+5)
    __shared__ float red[4];

    // ---------------- Phase 1: 2x2 mean pool (x10 scale) ----------------
    {
        const float* rbase = rgb + (size_t)n * 3 * 256 * 256;
#pragma unroll
        for (int it = 0; it < 7; it++) {
            int idx = it * 128 + tid;
            if (idx < 6 * 3 * 48) {
                int ci = idx % 48;
                int ch = (idx / 48) % 3;
                int rr = idx / 144;
                int cc = min(max(x0base - 8 + ci, 0), 127);   // clamp; garbage-safe
                int ry = min(y + rr, 127);
                const float* p = rbase + (size_t)ch * (256 * 256) + (2 * ry) * 256 + 2 * cc;
                float2 a = __ldg((const float2*)p);
                float2 b = __ldg((const float2*)(p + 256));
                pool[rr][ch][ci] = (a.x + a.y + b.x + b.y) * 2.5f;  // 0.25 mean * 10
            }
        }
    }
    __syncthreads();

    // ---------------- Phase 2: K2 + term1 ----------------
    float t1;
    {
        const int px = tid & 31;
        const int g  = tid >> 5;          // warp-uniform
        const int x  = x0base + px;

        if      (g == 0) t1 = phase2_slots<0>(pool, K2s, px, x, y);
        else if (g == 1) t1 = phase2_slots<1>(pool, K2s, px, x, y);
        else if (g == 2) t1 = phase2_slots<2>(pool, K2s, px, x, y);
        else             t1 = phase2_slots<3>(pool, K2s, px, x, y);

        if (g == 0) {  // OOB (zero-padded feature) taps, closed form, once per px
            const int c0 = px + 8;
            float r0 = pool[0][0][c0], g0 = pool[0][1][c0], b0 = pool[0][2][c0];
            int xl = max(x - 5, 0), xr = min(x + 5, WW - 1);
            int yl = max(y - 5, 0), yr = min(y + 5, HH - 1);
            float oob = 121.0f - (float)((xr - xl + 1) * (yr - yl + 1));
            float ep  = exp2f((float)(x * x + y * y) * (NEG_HALF_LOG2E / 36.0f));
            float ec  = exp2f(fmaf(r0, r0, fmaf(g0, g0, b0 * b0)) * NEG_HALF_LOG2E);
            t1 += oob * ep * (0.9f * ec + 0.1f);
        }
    }
    __syncthreads();

    // ---------------- Phase 3: term2 (packed f32x2 s-matrix) ----------------
    float t2 = 0.0f;
    if (tid < 112) {                      // 2 rowgroups x 7 cgroups x 8 quads
        const int q  = tid & 7;           // quad within 32 px
        const int cg = (tid >> 3) % 7;    // channels 3cg..3cg+2
        const int rg = tid / 56;          // rows rg*3 .. rg*3+2
        const int x0 = x0base + 4 * q;

        const float* ybase = Y + (size_t)n * NC * PL + (size_t)cg * 3 * PL;
        const bool pm2 = (x0 >= 8), pm1 = (x0 >= 4);
        const bool pp1 = (x0 <= 120), pp2 = (x0 <= 116);
        const float4 Z4 = {0.f, 0.f, 0.f, 0.f};

        u64 yp01[3], yp23[3];
#pragma unroll
        for (int c = 0; c < 3; c++) {
            float4 v = __ldg((const float4*)(ybase + (size_t)c * PL + y * WW + x0));
            yp01[c] = pk(v.x, v.y);
            yp23[c] = pk(v.z, v.w);
        }

        u64 acc01 = 0ull, acc23 = 0ull;   // packed (+0,+0)

#pragma unroll
        for (int rr = 0; rr < 3; rr++) {
            int r = rg * 3 + rr;
            if (y + r < HH) {
                const float* krow = &K2s[r * 11][0] + 4 * q;

                // ===== half A: d = 0..4, window floats x0-8 .. x0+3 =====
                {
                    u64 sA[5][2];
#pragma unroll
                    for (int d = 0; d < 5; d++) { sA[d][0] = 0ull; sA[d][1] = 0ull; }

#pragma unroll
                    for (int c = 0; c < 3; c++) {
                        const float* rb = ybase + (size_t)c * PL + (y + r) * WW + x0;
                        float w[12];
                        float4 v;
                        v = pm2 ? __ldg((const float4*)(rb - 8)) : Z4;
                        w[0] = v.x; w[1] = v.y; w[2] = v.z; w[3] = v.w;
                        v = pm1 ? __ldg((const float4*)(rb - 4)) : Z4;
                        w[4] = v.x; w[5] = v.y; w[6] = v.z; w[7] = v.w;
                        v = __ldg((const float4*)rb);
                        w[8] = v.x; w[9] = v.y; w[10] = v.z; w[11] = v.w;

                        u64 P[10];
#pragma unroll
                        for (int a = 3; a <= 9; a++) P[a] = pk(w[a], w[a + 1]);

                        // scalar form: sA[d][p] += yp[c][p] * w[3+p+d]
#pragma unroll
                        for (int d = 0; d < 5; d++) {
                            fma2(sA[d][0], yp01[c], P[3 + d]);
                            fma2(sA[d][1], yp23[c], P[5 + d]);
                        }
                    }
#pragma unroll
                    for (int d = 0; d < 5; d++) {
                        u64 k01 = *reinterpret_cast<const u64*>(krow + d * 32);
                        u64 k23 = *reinterpret_cast<const u64*>(krow + d * 32 + 2);
                        fma2(acc01, k01, sA[d][0]);
                        fma2(acc23, k23, sA[d][1]);
                    }
                }

                // ===== half B: d = 5..10, window floats x0 .. x0+11 =====
                {
                    u64 sB[6][2];
#pragma unroll
                    for (int d = 0; d < 6; d++) { sB[d][0] = 0ull; sB[d][1] = 0ull; }

#pragma unroll
                    for (int c = 0; c < 3; c++) {
                        const float* rb = ybase + (size_t)c * PL + (y + r) * WW + x0;
                        float w[12];
                        float4 v;
                        v = __ldg((const float4*)rb);
                        w[0] = v.x; w[1] = v.y; w[2] = v.z; w[3] = v.w;
                        v = pp1 ? __ldg((const float4*)(rb + 4)) : Z4;
                        w[4] = v.x; w[5] = v.y; w[6] = v.z; w[7] = v.w;
                        v = pp2 ? __ldg((const float4*)(rb + 8)) : Z4;
                        w[8] = v.x; w[9] = v.y; w[10] = v.z; w[11] = v.w;

                        u64 P[8];
#pragma unroll
                        for (int a = 0; a <= 7; a++) P[a] = pk(w[a], w[a + 1]);

                        // scalar form: sB[d-5][p] += yp[c][p] * w[p+d-5]
#pragma unroll
                        for (int d = 5; d < 11; d++) {
                            fma2(sB[d - 5][0], yp01[c], P[d - 5]);
                            fma2(sB[d - 5][1], yp23[c], P[d - 3]);
                        }
                    }
#pragma unroll
                    for (int d = 5; d < 11; d++) {
                        u64 k01 = *reinterpret_cast<const u64*>(krow + d * 32);
                        u64 k23 = *reinterpret_cast<const u64*>(krow + d * 32 + 2);
                        fma2(acc01, k01, sB[d - 5][0]);
                        fma2(acc23, k23, sB[d - 5][1]);
                    }
                }
            }
        }
        float2 a01 = unpk(acc01);
        float2 a23 = unpk(acc23);
        t2 = (a01.x + a01.y) + (a23.x + a23.y);
    }

    // ---------------- Epilogue: reduce + finalize ----------------
    float v = t1 - t2;
#pragma unroll
    for (int sft = 16; sft > 0; sft >>= 1)
        v += __shfl_down_sync(0xFFFFFFFFu, v, sft);

    int lane = tid & 31, warp = tid >> 5;
    if (lane == 0) red[warp] = v;
    __syncthreads();
    if (tid == 0) {
        float bs = (red[0] + red[1]) + (red[2] + red[3]);
        int slot = ((blockIdx.y & 7) << 2) | blockIdx.x;   // 32 spread slots
        atomicAdd(&g_accs[slot], (double)bs);
        __threadfence();
        unsigned old = atomicAdd(&g_cnt, 1u);
        if (old == (unsigned)(NBLK - 1)) {
            double tot = 0.0;
#pragma unroll
            for (int i = 0; i < 32; i++) {
                tot += atomicAdd(&g_accs[i], 0.0);
                g_accs[i] = 0.0;                 // self-reset for graph replay
            }
            out[0] = (float)(tot / (double)(NIMG * HH * WW));
            g_cnt = 0u;
        }
    }
}

extern "C" void kernel_launch(void* const* d_in, const int* in_sizes, int n_in,
                              void* d_out, int out_size) {
    const float* y   = (const float*)d_in[0];
    const float* rgb = (const float*)d_in[1];
    if (n_in >= 2 && in_sizes[0] == NIMG * 3 * 256 * 256) {
        const float* t = y; y = rgb; rgb = t;
    }

    dim3 grid(4, HH, NIMG);   // 1024 blocks, single wave at 8 blocks/SM
    crf_fused<<<grid, 128>>>(y, rgb, (float*)d_out);
}

// round 10
// speedup vs baseline: 1.0132x; 1.0132x over previous
#include <cuda_runtime.h>

#define HH 128
#define WW 128
#define NIMG 2
#define NC 21
#define PL (HH * WW)
#define NBLK (4 * HH * NIMG)   // 1024 blocks: (xquarter, y, n)

// exp(-0.5 v) = exp2(v * -0.72134752)
#define NEG_HALF_LOG2E (-0.72134752f)

__device__ double   g_accs[32];   // spread accumulators (zero-init; self-reset)
__device__ unsigned g_cnt;

typedef unsigned long long u64;

// ---- packed f32x2 helpers (FFMA2 path; ptxas never emits these from C++) ----
__device__ __forceinline__ u64 pk(float lo, float hi) {
    u64 r;
    asm("mov.b64 %0, {%1, %2};" : "=l"(r) : "f"(lo), "f"(hi));
    return r;
}
__device__ __forceinline__ void fma2(u64& d, u64 a, u64 b) {
    asm("fma.rn.f32x2 %0, %1, %2, %0;" : "+l"(d) : "l"(a), "l"(b));
}
__device__ __forceinline__ float2 unpk(u64 v) {
    float lo, hi;
    asm("mov.b64 {%0, %1}, %2;" : "=f"(lo), "=f"(hi) : "l"(v));
    return make_float2(lo, hi);
}
// 16B shared load -> two packed f32x2 operands, zero pack MOVs
__device__ __forceinline__ void lds_v2u64(u64& a, u64& b, const float* p) {
    unsigned saddr = (unsigned)__cvta_generic_to_shared(p);
    asm("ld.shared.v2.b64 {%0, %1}, [%2];" : "=l"(a), "=l"(b) : "r"(saddr));
}

// exp(-k^2/72) for k = 0..5 (compile-time folded)
__device__ __forceinline__ constexpr float exy_tab(int k) {
    constexpr float E[6] = {1.0f, 0.98620712f, 0.94595947f,
                            0.88249690f, 0.80073740f, 0.70664828f};
    return E[k];
}

// ---------------------------------------------------------------------------
// Phase-2 worker: warp-group G handles slots with slot%4 == G.
// (r, dx, slot, exy) compile-time. Non-forward slots written 0.
// ---------------------------------------------------------------------------
template <int G>
__device__ __forceinline__ float phase2_slots(const float (*pool)[3][48],
                                              float (*K2s)[32],
                                              int px, int x, int y) {
    const int c0 = px + 8;
    const float r0 = pool[0][0][c0];
    const float g0 = pool[0][1][c0];
    const float b0 = pool[0][2][c0];
    float t1 = 0.0f;
#pragma unroll
    for (int r = 0; r <= 5; r++) {
#pragma unroll
        for (int dxi = 0; dxi < 11; dxi++) {
            const int slot = r * 11 + dxi;
            if ((slot & 3) == G) {
                const int dx = dxi - 5;
                const bool fwd = (r > 0) || (dx > 0);
                float k2 = 0.0f;
                if (fwd && (y + r < HH) && ((unsigned)(x + dx) < (unsigned)WW)) {
                    const float exy = exy_tab(r) * exy_tab(dx < 0 ? -dx : dx);
                    const int ci = c0 + dx;
                    float dr = pool[r][0][ci] - r0;
                    float dg = pool[r][1][ci] - g0;
                    float db = pool[r][2][ci] - b0;
                    float q  = fmaf(dr, dr, fmaf(dg, dg, db * db));
                    float e  = exp2f(q * NEG_HALF_LOG2E);
                    k2 = fmaf(1.8f * exy, e, 0.2f * exy);
                }
                t1 += k2;
                K2s[slot][px] = k2;
            }
        }
    }
    return t1;
}

// ---------------------------------------------------------------------------
// ONE fused kernel. Block = quarter-row (32 px), 128 threads, 7 blocks/SM
// (no reg spills; 1036 CTA capacity >= 1024 grid: single wave).
// Phase 3 packed f32x2; k2 pairs loaded via ld.shared.v2.b64 (no packs).
// ---------------------------------------------------------------------------
__global__ void __launch_bounds__(128, 7) crf_fused(const float* __restrict__ Y,
                                                    const float* __restrict__ rgb,
                                                    float* __restrict__ out) {
    const int xq = blockIdx.x;           // 0..3
    const int y  = blockIdx.y;           // 0..127
    const int n  = blockIdx.z;           // 0..1
    const int x0base = xq * 32;
    const int tid = threadIdx.x;

    __shared__ float pool[6][3][48];                     // pooled rgb + halo
    __shared__ __align__(16) float K2s[66][32];          // slot = r*11 + (dx+5)
    __shared__ float red[4];

    // ---- hoisted: center-Y loads (latency overlapped with phases 1-2) ----
    const int q_  = tid & 7;
    const int cg_ = (tid >> 3) % 7;
    const int x0_ = x0base + 4 * q_;
    const float* ybase_ = Y + (size_t)n * NC * PL + (size_t)cg_ * 3 * PL;
    u64 yp01[3], yp23[3];
#pragma unroll
    for (int c = 0; c < 3; c++) {
        float4 v = __ldg((const float4*)(ybase_ + (size_t)c * PL + y * WW + x0_));
        yp01[c] = pk(v.x, v.y);
        yp23[c] = pk(v.z, v.w);
    }

    // ---------------- Phase 1: 2x2 mean pool (x10 scale) ----------------
    {
        const float* rbase = rgb + (size_t)n * 3 * 256 * 256;
#pragma unroll
        for (int it = 0; it < 7; it++) {
            int idx = it * 128 + tid;
            if (idx < 6 * 3 * 48) {
                int ci = idx % 48;
                int ch = (idx / 48) % 3;
                int rr = idx / 144;
                int cc = min(max(x0base - 8 + ci, 0), 127);   // clamp; garbage-safe
                int ry = min(y + rr, 127);
                const float* p = rbase + (size_t)ch * (256 * 256) + (2 * ry) * 256 + 2 * cc;
                float2 a = __ldg((const float2*)p);
                float2 b = __ldg((const float2*)(p + 256));
                pool[rr][ch][ci] = (a.x + a.y + b.x + b.y) * 2.5f;  // 0.25 mean * 10
            }
        }
    }
    __syncthreads();

    // ---------------- Phase 2: K2 + term1 ----------------
    float t1;
    {
        const int px = tid & 31;
        const int g  = tid >> 5;          // warp-uniform
        const int x  = x0base + px;

        if      (g == 0) t1 = phase2_slots<0>(pool, K2s, px, x, y);
        else if (g == 1) t1 = phase2_slots<1>(pool, K2s, px, x, y);
        else if (g == 2) t1 = phase2_slots<2>(pool, K2s, px, x, y);
        else             t1 = phase2_slots<3>(pool, K2s, px, x, y);

        if (g == 0) {  // OOB (zero-padded feature) taps, closed form, once per px
            const int c0 = px + 8;
            float r0 = pool[0][0][c0], g0 = pool[0][1][c0], b0 = pool[0][2][c0];
            int xl = max(x - 5, 0), xr = min(x + 5, WW - 1);
            int yl = max(y - 5, 0), yr = min(y + 5, HH - 1);
            float oob = 121.0f - (float)((xr - xl + 1) * (yr - yl + 1));
            float ep  = exp2f((float)(x * x + y * y) * (NEG_HALF_LOG2E / 36.0f));
            float ec  = exp2f(fmaf(r0, r0, fmaf(g0, g0, b0 * b0)) * NEG_HALF_LOG2E);
            t1 += oob * ep * (0.9f * ec + 0.1f);
        }
    }
    __syncthreads();

    // ---------------- Phase 3: term2 (packed f32x2 s-matrix) ----------------
    float t2 = 0.0f;
    if (tid < 112) {                      // 2 rowgroups x 7 cgroups x 8 quads
        const int q  = q_;
        const int x0 = x0_;
        const int rg = tid / 56;          // rows rg*3 .. rg*3+2
        const float* ybase = ybase_;

        const bool pm2 = (x0 >= 8), pm1 = (x0 >= 4);
        const bool pp1 = (x0 <= 120), pp2 = (x0 <= 116);
        const float4 Z4 = {0.f, 0.f, 0.f, 0.f};

        u64 acc01 = 0ull, acc23 = 0ull;   // packed (+0,+0)

#pragma unroll
        for (int rr = 0; rr < 3; rr++) {
            int r = rg * 3 + rr;
            if (y + r < HH) {
                const float* krow = &K2s[r * 11][0] + 4 * q;

                // ===== half A: d = 0..4, window floats x0-8 .. x0+3 =====
                {
                    u64 sA[5][2];
#pragma unroll
                    for (int d = 0; d < 5; d++) { sA[d][0] = 0ull; sA[d][1] = 0ull; }

#pragma unroll
                    for (int c = 0; c < 3; c++) {
                        const float* rb = ybase + (size_t)c * PL + (y + r) * WW + x0;
                        float w[12];
                        float4 v;
                        v = pm2 ? __ldg((const float4*)(rb - 8)) : Z4;
                        w[0] = v.x; w[1] = v.y; w[2] = v.z; w[3] = v.w;
                        v = pm1 ? __ldg((const float4*)(rb - 4)) : Z4;
                        w[4] = v.x; w[5] = v.y; w[6] = v.z; w[7] = v.w;
                        v = __ldg((const float4*)rb);
                        w[8] = v.x; w[9] = v.y; w[10] = v.z; w[11] = v.w;

                        u64 P[10];
#pragma unroll
                        for (int a = 3; a <= 9; a++) P[a] = pk(w[a], w[a + 1]);

                        // scalar form: sA[d][p] += yp[c][p] * w[3+p+d]
#pragma unroll
                        for (int d = 0; d < 5; d++) {
                            fma2(sA[d][0], yp01[c], P[3 + d]);
                            fma2(sA[d][1], yp23[c], P[5 + d]);
                        }
                    }
#pragma unroll
                    for (int d = 0; d < 5; d++) {
                        u64 k01, k23;
                        lds_v2u64(k01, k23, krow + d * 32);
                        fma2(acc01, k01, sA[d][0]);
                        fma2(acc23, k23, sA[d][1]);
                    }
                }

                // ===== half B: d = 5..10, window floats x0 .. x0+11 =====
                {
                    u64 sB[6][2];
#pragma unroll
                    for (int d = 0; d < 6; d++) { sB[d][0] = 0ull; sB[d][1] = 0ull; }

#pragma unroll
                    for (int c = 0; c < 3; c++) {
                        const float* rb = ybase + (size_t)c * PL + (y + r) * WW + x0;
                        float w[12];
                        float4 v;
                        v = __ldg((const float4*)rb);
                        w[0] = v.x; w[1] = v.y; w[2] = v.z; w[3] = v.w;
                        v = pp1 ? __ldg((const float4*)(rb + 4)) : Z4;
                        w[4] = v.x; w[5] = v.y; w[6] = v.z; w[7] = v.w;
                        v = pp2 ? __ldg((const float4*)(rb + 8)) : Z4;
                        w[8] = v.x; w[9] = v.y; w[10] = v.z; w[11] = v.w;

                        u64 P[8];
#pragma unroll
                        for (int a = 0; a <= 7; a++) P[a] = pk(w[a], w[a + 1]);

                        // scalar form: sB[d-5][p] += yp[c][p] * w[p+d-5]
#pragma unroll
                        for (int d = 5; d < 11; d++) {
                            fma2(sB[d - 5][0], yp01[c], P[d - 5]);
                            fma2(sB[d - 5][1], yp23[c], P[d - 3]);
                        }
                    }
#pragma unroll
                    for (int d = 5; d < 11; d++) {
                        u64 k01, k23;
                        lds_v2u64(k01, k23, krow + d * 32);
                        fma2(acc01, k01, sB[d - 5][0]);
                        fma2(acc23, k23, sB[d - 5][1]);
                    }
                }
            }
        }
        float2 a01 = unpk(acc01);
        float2 a23 = unpk(acc23);
        t2 = (a01.x + a01.y) + (a23.x + a23.y);
    }

    // ---------------- Epilogue: reduce + finalize ----------------
    float v = t1 - t2;
#pragma unroll
    for (int sft = 16; sft > 0; sft >>= 1)
        v += __shfl_down_sync(0xFFFFFFFFu, v, sft);

    int lane = tid & 31, warp = tid >> 5;
    if (lane == 0) red[warp] = v;
    __syncthreads();
    if (tid == 0) {
        float bs = (red[0] + red[1]) + (red[2] + red[3]);
        int slot = ((blockIdx.y & 7) << 2) | blockIdx.x;   // 32 spread slots
        atomicAdd(&g_accs[slot], (double)bs);
        __threadfence();
        unsigned old = atomicAdd(&g_cnt, 1u);
        if (old == (unsigned)(NBLK - 1)) {
            double tot = 0.0;
#pragma unroll
            for (int i = 0; i < 32; i++) {
                tot += atomicAdd(&g_accs[i], 0.0);
                g_accs[i] = 0.0;                 // self-reset for graph replay
            }
            out[0] = (float)(tot / (double)(NIMG * HH * WW));
            g_cnt = 0u;
        }
    }
}

extern "C" void kernel_launch(void* const* d_in, const int* in_sizes, int n_in,
                              void* d_out, int out_size) {
    const float* y   = (const float*)d_in[0];
    const float* rgb = (const float*)d_in[1];
    if (n_in >= 2 && in_sizes[0] == NIMG * 3 * 256 * 256) {
        const float* t = y; y = rgb; rgb = t;
    }

    dim3 grid(4, HH, NIMG);   // 1024 blocks, single wave at 7 blocks/SM
    crf_fused<<<grid, 128>>>(y, rgb, (float*)d_out);
}